// round 1
// baseline (speedup 1.0000x reference)
#include <cuda_runtime.h>
#include <math.h>

#define N_NODES 100000
#define N_EDGES 1600000
#define D 128
#define NEG_SLOPE 0.2f
#define INV_SQRT_D 0.08838834764831843f

// ---------------- scratch (no allocs allowed) ----------------
__device__ float g_hq[N_NODES * D];      // x @ W_q
__device__ float g_kact[N_NODES * D];    // leaky_relu(x @ W_k)
__device__ float g_hproj[N_NODES * D];   // x @ W_l + b_l
__device__ float g_qagg[N_NODES * D];    // segment_sum(h_q[col], row)
__device__ float g_hprime[N_NODES * D];  // output accumulator
__device__ float g_scores[N_EDGES];      // scores, then exp(scores - max)
__device__ unsigned int g_rowmax[N_NODES];
__device__ float g_rowsum[N_NODES];

// monotone float<->uint encoding for atomicMax on signed floats
__device__ __forceinline__ unsigned int enc_f(float f) {
    unsigned int u = __float_as_uint(f);
    return (u & 0x80000000u) ? ~u : (u | 0x80000000u);
}
__device__ __forceinline__ float dec_f(unsigned int u) {
    return (u & 0x80000000u) ? __uint_as_float(u ^ 0x80000000u)
                             : __uint_as_float(~u);
}

__device__ __forceinline__ float leaky(float v) {
    return v > 0.0f ? v : NEG_SLOPE * v;
}

// ---------------- 0: zero scratch accumulators ----------------
__global__ void zero_kernel() {
    int i = blockIdx.x * blockDim.x + threadIdx.x;
    const int total4 = (N_NODES * D) / 4;  // 3.2M float4
    if (i < total4) {
        float4 z = make_float4(0.f, 0.f, 0.f, 0.f);
        ((float4*)g_qagg)[i] = z;
        ((float4*)g_hprime)[i] = z;
    }
    if (i < N_NODES) {
        g_rowmax[i] = 0u;   // below enc of any finite float
        g_rowsum[i] = 0.f;
    }
}

// ---------------- 1: fused 3-way GEMM ----------------
// blockIdx.y: 0 -> h_q = x@W_q ; 1 -> k_act = leaky(x@W_k) ; 2 -> h_proj = x@W_l + b
#define BM 128
#define BN 128
#define BK 16
#define TM 8
#define TN 8

__global__ __launch_bounds__(256, 2)
void gemm3_kernel(const float* __restrict__ x,
                  const float* __restrict__ Wq,
                  const float* __restrict__ Wk,
                  const float* __restrict__ Wl,
                  const float* __restrict__ bl) {
    __shared__ float As[BK][BM];       // x tile, transposed
    __shared__ float Bs[BK][BN + 4];   // W tile (padded)

    const int wi = blockIdx.y;
    const float* __restrict__ W = (wi == 0) ? Wq : ((wi == 1) ? Wk : Wl);
    float* __restrict__ out = (wi == 0) ? g_hq : ((wi == 1) ? g_kact : g_hproj);

    const int rowBase = blockIdx.x * BM;
    const int tid = threadIdx.x;
    const int tx = tid & 15;
    const int ty = tid >> 4;

    float acc[TM][TN];
#pragma unroll
    for (int i = 0; i < TM; i++)
#pragma unroll
        for (int j = 0; j < TN; j++) acc[i][j] = 0.f;

    for (int k0 = 0; k0 < D; k0 += BK) {
        // load x tile: BM x BK, 512 float4 across 256 threads
#pragma unroll
        for (int i = tid; i < (BM * BK) / 4; i += 256) {
            int r = i >> 2;               // BK/4 = 4 float4 per row
            int kk4 = (i & 3) << 2;
            int gr = rowBase + r;
            float4 v = make_float4(0.f, 0.f, 0.f, 0.f);
            if (gr < N_NODES)
                v = *(const float4*)(x + (size_t)gr * D + k0 + kk4);
            As[kk4 + 0][r] = v.x;
            As[kk4 + 1][r] = v.y;
            As[kk4 + 2][r] = v.z;
            As[kk4 + 3][r] = v.w;
        }
        // load W tile: BK x BN, 512 float4
#pragma unroll
        for (int i = tid; i < (BK * BN) / 4; i += 256) {
            int kk = i >> 5;              // BN/4 = 32 float4 per row
            int c4 = (i & 31) << 2;
            float4 v = *(const float4*)(W + (size_t)(k0 + kk) * D + c4);
            Bs[kk][c4 + 0] = v.x;
            Bs[kk][c4 + 1] = v.y;
            Bs[kk][c4 + 2] = v.z;
            Bs[kk][c4 + 3] = v.w;
        }
        __syncthreads();

#pragma unroll
        for (int kk = 0; kk < BK; kk++) {
            float a[TM], b[TN];
#pragma unroll
            for (int i = 0; i < TM; i++) a[i] = As[kk][ty * TM + i];
#pragma unroll
            for (int j = 0; j < TN; j++) b[j] = Bs[kk][tx * TN + j];
#pragma unroll
            for (int i = 0; i < TM; i++)
#pragma unroll
                for (int j = 0; j < TN; j++) acc[i][j] += a[i] * b[j];
        }
        __syncthreads();
    }

    // epilogue
#pragma unroll
    for (int i = 0; i < TM; i++) {
        int gr = rowBase + ty * TM + i;
        if (gr >= N_NODES) continue;
#pragma unroll
        for (int j = 0; j < TN; j += 4) {
            int gc = tx * TN + j;
            float4 v = make_float4(acc[i][j], acc[i][j + 1],
                                   acc[i][j + 2], acc[i][j + 3]);
            if (wi == 1) {
                v.x = leaky(v.x); v.y = leaky(v.y);
                v.z = leaky(v.z); v.w = leaky(v.w);
            } else if (wi == 2) {
                v.x += __ldg(bl + gc + 0);
                v.y += __ldg(bl + gc + 1);
                v.z += __ldg(bl + gc + 2);
                v.w += __ldg(bl + gc + 3);
            }
            *(float4*)(out + (size_t)gr * D + gc) = v;
        }
    }
}

// ---------------- 2: q_agg[row] += h_q[col]  (warp per edge) ----------------
__global__ __launch_bounds__(256)
void qagg_kernel(const int* __restrict__ row, const int* __restrict__ col) {
    int e = (blockIdx.x * blockDim.x + threadIdx.x) >> 5;
    if (e >= N_EDGES) return;
    int lane = threadIdx.x & 31;
    int r = __ldg(row + e);
    int c = __ldg(col + e);
    float4 v = *(const float4*)(g_hq + (size_t)c * D + lane * 4);
    float* dst = g_qagg + (size_t)r * D + lane * 4;
    atomicAdd(dst + 0, v.x);
    atomicAdd(dst + 1, v.y);
    atomicAdd(dst + 2, v.z);
    atomicAdd(dst + 3, v.w);
}

// ---------------- 3: scores + segment max  (warp per edge) ----------------
__global__ __launch_bounds__(256)
void score_kernel(const int* __restrict__ row, const int* __restrict__ col) {
    int e = (blockIdx.x * blockDim.x + threadIdx.x) >> 5;
    if (e >= N_EDGES) return;
    int lane = threadIdx.x & 31;
    int r = __ldg(row + e);
    int c = __ldg(col + e);
    float4 k = *(const float4*)(g_kact + (size_t)r * D + lane * 4);
    float4 q = *(const float4*)(g_qagg + (size_t)c * D + lane * 4);
    float s = k.x * q.x + k.y * q.y + k.z * q.z + k.w * q.w;
#pragma unroll
    for (int o = 16; o > 0; o >>= 1) s += __shfl_xor_sync(0xFFFFFFFFu, s, o);
    if (lane == 0) {
        s *= INV_SQRT_D;
        g_scores[e] = s;
        atomicMax(&g_rowmax[r], enc_f(s));
    }
}

// ---------------- 4: exp + segment sum  (thread per edge) ----------------
__global__ __launch_bounds__(256)
void expsum_kernel(const int* __restrict__ row) {
    int e = blockIdx.x * blockDim.x + threadIdx.x;
    if (e >= N_EDGES) return;
    int r = __ldg(row + e);
    float m = dec_f(g_rowmax[r]);
    float ex = expf(g_scores[e] - m);
    g_scores[e] = ex;
    atomicAdd(&g_rowsum[r], ex);
}

// ---------------- 5: h_prime[row] += alpha * h_proj[col]  (warp per edge) ----
__global__ __launch_bounds__(256)
void weighted_kernel(const int* __restrict__ row, const int* __restrict__ col) {
    int e = (blockIdx.x * blockDim.x + threadIdx.x) >> 5;
    if (e >= N_EDGES) return;
    int lane = threadIdx.x & 31;
    int r = __ldg(row + e);
    int c = __ldg(col + e);
    float alpha = g_scores[e] / (g_rowsum[r] + 1e-8f);
    float4 v = *(const float4*)(g_hproj + (size_t)c * D + lane * 4);
    float* dst = g_hprime + (size_t)r * D + lane * 4;
    atomicAdd(dst + 0, alpha * v.x);
    atomicAdd(dst + 1, alpha * v.y);
    atomicAdd(dst + 2, alpha * v.z);
    atomicAdd(dst + 3, alpha * v.w);
}

// ---------------- 6: final leaky relu ----------------
__global__ __launch_bounds__(256)
void final_kernel(float* __restrict__ out) {
    int i = blockIdx.x * blockDim.x + threadIdx.x;
    const int total4 = (N_NODES * D) / 4;
    if (i >= total4) return;
    float4 v = ((const float4*)g_hprime)[i];
    v.x = leaky(v.x);
    v.y = leaky(v.y);
    v.z = leaky(v.z);
    v.w = leaky(v.w);
    ((float4*)out)[i] = v;
}

// ---------------- launch ----------------
extern "C" void kernel_launch(void* const* d_in, const int* in_sizes, int n_in,
                              void* d_out, int out_size) {
    const float* x  = (const float*)d_in[0];
    const int*  ei  = (const int*)d_in[1];   // [2, E] row-major
    const float* Wq = (const float*)d_in[2];
    const float* Wk = (const float*)d_in[3];
    // d_in[4] = W_v : dead code in reference, never used
    const float* Wl = (const float*)d_in[5];
    const float* bl = (const float*)d_in[6];
    float* out = (float*)d_out;

    const int* row = ei;             // edge_index[0]
    const int* col = ei + N_EDGES;   // edge_index[1]

    // 0: zero accumulators
    {
        int n = (N_NODES * D) / 4;   // also covers N_NODES scalar arrays
        zero_kernel<<<(n + 255) / 256, 256>>>();
    }
    // 1: fused GEMMs
    {
        dim3 grid((N_NODES + BM - 1) / BM, 3);
        gemm3_kernel<<<grid, 256>>>(x, Wq, Wk, Wl, bl);
    }
    // 2-5: edge phase
    {
        int warps_grid = (N_EDGES * 32 + 255) / 256;
        qagg_kernel<<<warps_grid, 256>>>(row, col);
        score_kernel<<<warps_grid, 256>>>(row, col);
        expsum_kernel<<<(N_EDGES + 255) / 256, 256>>>(row);
        weighted_kernel<<<warps_grid, 256>>>(row, col);
    }
    // 6: output
    {
        int n = (N_NODES * D) / 4;
        final_kernel<<<(n + 255) / 256, 256>>>(out);
    }
}

// round 2
// speedup vs baseline: 2.6583x; 2.6583x over previous
#include <cuda_runtime.h>
#include <math.h>

#define N_NODES 100000
#define N_EDGES 1600000
#define D 128
#define NEG_SLOPE 0.2f
#define INV_SQRT_D 0.08838834764831843f

#define SCAN_CHUNK 512
#define NBLK_SCAN ((N_NODES + SCAN_CHUNK - 1) / SCAN_CHUNK)   // 196

// ---------------- scratch (no allocs allowed) ----------------
__device__ float g_hq[N_NODES * D];      // x @ W_q
__device__ float g_kact[N_NODES * D];    // leaky_relu(x @ W_k)
__device__ float g_hproj[N_NODES * D];   // x @ W_l + b_l
__device__ float g_qagg[N_NODES * D];    // segment_sum(h_q[col], row)
__device__ float g_escore[N_EDGES];      // exp(score), CSR order
__device__ float g_rinv[N_NODES];        // 1 / (rowsum + 1e-8)
__device__ int   g_cnt[N_NODES];
__device__ int   g_off[N_NODES + 1];
__device__ int   g_cursor[N_NODES];
__device__ int   g_ecol[N_EDGES];        // col indices sorted by row
__device__ int   g_blocksum[NBLK_SCAN];
__device__ int   g_blockbase[NBLK_SCAN];

__device__ __forceinline__ float leaky(float v) {
    return v > 0.0f ? v : NEG_SLOPE * v;
}

// ================= CSR build =================
__global__ void zero_cnt_kernel() {
    int i = blockIdx.x * blockDim.x + threadIdx.x;
    if (i < N_NODES) g_cnt[i] = 0;
}

__global__ void hist_kernel(const int* __restrict__ row) {
    int e = blockIdx.x * blockDim.x + threadIdx.x;
    if (e < N_EDGES) atomicAdd(&g_cnt[__ldg(row + e)], 1);
}

__global__ void scan1_kernel() {
    __shared__ int s[SCAN_CHUNK];
    int b = blockIdx.x, t = threadIdx.x;
    int i = b * SCAN_CHUNK + t;
    int v = (i < N_NODES) ? g_cnt[i] : 0;
    s[t] = v;
    __syncthreads();
    for (int off = 1; off < SCAN_CHUNK; off <<= 1) {
        int add = (t >= off) ? s[t - off] : 0;
        __syncthreads();
        s[t] += add;
        __syncthreads();
    }
    if (i < N_NODES) g_off[i] = s[t] - v;   // exclusive, no base yet
    if (t == SCAN_CHUNK - 1) g_blocksum[b] = s[t];
}

__global__ void scan2_kernel() {
    __shared__ int s[256];
    int t = threadIdx.x;
    int v = (t < NBLK_SCAN) ? g_blocksum[t] : 0;
    s[t] = v;
    __syncthreads();
    for (int off = 1; off < 256; off <<= 1) {
        int add = (t >= off) ? s[t - off] : 0;
        __syncthreads();
        s[t] += add;
        __syncthreads();
    }
    if (t < NBLK_SCAN) g_blockbase[t] = s[t] - v;   // exclusive
}

__global__ void scan3_kernel() {
    int i = blockIdx.x * blockDim.x + threadIdx.x;
    if (i < N_NODES) {
        int o = g_off[i] + g_blockbase[i / SCAN_CHUNK];
        g_off[i] = o;
        g_cursor[i] = o;
    }
    if (i == 0) g_off[N_NODES] = N_EDGES;
}

__global__ void scatter_kernel(const int* __restrict__ row,
                               const int* __restrict__ col) {
    int e = blockIdx.x * blockDim.x + threadIdx.x;
    if (e >= N_EDGES) return;
    int r = __ldg(row + e);
    int pos = atomicAdd(&g_cursor[r], 1);
    g_ecol[pos] = __ldg(col + e);
}

// ================= fused 3-way GEMM =================
#define BM 128
#define BN 128
#define BK 16
#define TM 8
#define TN 8

__global__ __launch_bounds__(256, 2)
void gemm3_kernel(const float* __restrict__ x,
                  const float* __restrict__ Wq,
                  const float* __restrict__ Wk,
                  const float* __restrict__ Wl,
                  const float* __restrict__ bl) {
    __shared__ float As[BK][BM];
    __shared__ float Bs[BK][BN + 4];

    const int wi = blockIdx.y;
    const float* __restrict__ W = (wi == 0) ? Wq : ((wi == 1) ? Wk : Wl);
    float* __restrict__ out = (wi == 0) ? g_hq : ((wi == 1) ? g_kact : g_hproj);

    const int rowBase = blockIdx.x * BM;
    const int tid = threadIdx.x;
    const int tx = tid & 15;
    const int ty = tid >> 4;

    float acc[TM][TN];
#pragma unroll
    for (int i = 0; i < TM; i++)
#pragma unroll
        for (int j = 0; j < TN; j++) acc[i][j] = 0.f;

    for (int k0 = 0; k0 < D; k0 += BK) {
#pragma unroll
        for (int i = tid; i < (BM * BK) / 4; i += 256) {
            int r = i >> 2;
            int kk4 = (i & 3) << 2;
            int gr = rowBase + r;
            float4 v = make_float4(0.f, 0.f, 0.f, 0.f);
            if (gr < N_NODES)
                v = *(const float4*)(x + (size_t)gr * D + k0 + kk4);
            As[kk4 + 0][r] = v.x;
            As[kk4 + 1][r] = v.y;
            As[kk4 + 2][r] = v.z;
            As[kk4 + 3][r] = v.w;
        }
#pragma unroll
        for (int i = tid; i < (BK * BN) / 4; i += 256) {
            int kk = i >> 5;
            int c4 = (i & 31) << 2;
            float4 v = *(const float4*)(W + (size_t)(k0 + kk) * D + c4);
            Bs[kk][c4 + 0] = v.x;
            Bs[kk][c4 + 1] = v.y;
            Bs[kk][c4 + 2] = v.z;
            Bs[kk][c4 + 3] = v.w;
        }
        __syncthreads();

#pragma unroll
        for (int kk = 0; kk < BK; kk++) {
            float a[TM], b[TN];
#pragma unroll
            for (int i = 0; i < TM; i++) a[i] = As[kk][ty * TM + i];
#pragma unroll
            for (int j = 0; j < TN; j++) b[j] = Bs[kk][tx * TN + j];
#pragma unroll
            for (int i = 0; i < TM; i++)
#pragma unroll
                for (int j = 0; j < TN; j++) acc[i][j] += a[i] * b[j];
        }
        __syncthreads();
    }

#pragma unroll
    for (int i = 0; i < TM; i++) {
        int gr = rowBase + ty * TM + i;
        if (gr >= N_NODES) continue;
#pragma unroll
        for (int j = 0; j < TN; j += 4) {
            int gc = tx * TN + j;
            float4 v = make_float4(acc[i][j], acc[i][j + 1],
                                   acc[i][j + 2], acc[i][j + 3]);
            if (wi == 1) {
                v.x = leaky(v.x); v.y = leaky(v.y);
                v.z = leaky(v.z); v.w = leaky(v.w);
            } else if (wi == 2) {
                v.x += __ldg(bl + gc + 0);
                v.y += __ldg(bl + gc + 1);
                v.z += __ldg(bl + gc + 2);
                v.w += __ldg(bl + gc + 3);
            }
            *(float4*)(out + (size_t)gr * D + gc) = v;
        }
    }
}

// ================= edge phase (warp per destination node, CSR) =============

// q_agg[node] = sum over incoming edges of h_q[col]
__global__ __launch_bounds__(256)
void qagg_csr_kernel() {
    int node = (blockIdx.x * blockDim.x + threadIdx.x) >> 5;
    if (node >= N_NODES) return;
    int lane = threadIdx.x & 31;
    int beg = g_off[node], end = g_off[node + 1];

    float4 acc = make_float4(0.f, 0.f, 0.f, 0.f);
    for (int e0 = beg; e0 < end; e0 += 32) {
        int myc = (e0 + lane < end) ? g_ecol[e0 + lane] : 0;
        int n = min(32, end - e0);
        int j = 0;
        for (; j + 4 <= n; j += 4) {
            int c0 = __shfl_sync(0xffffffffu, myc, j + 0);
            int c1 = __shfl_sync(0xffffffffu, myc, j + 1);
            int c2 = __shfl_sync(0xffffffffu, myc, j + 2);
            int c3 = __shfl_sync(0xffffffffu, myc, j + 3);
            float4 v0 = *(const float4*)(g_hq + (size_t)c0 * D + lane * 4);
            float4 v1 = *(const float4*)(g_hq + (size_t)c1 * D + lane * 4);
            float4 v2 = *(const float4*)(g_hq + (size_t)c2 * D + lane * 4);
            float4 v3 = *(const float4*)(g_hq + (size_t)c3 * D + lane * 4);
            acc.x += v0.x + v1.x + v2.x + v3.x;
            acc.y += v0.y + v1.y + v2.y + v3.y;
            acc.z += v0.z + v1.z + v2.z + v3.z;
            acc.w += v0.w + v1.w + v2.w + v3.w;
        }
        for (; j < n; j++) {
            int c = __shfl_sync(0xffffffffu, myc, j);
            float4 v = *(const float4*)(g_hq + (size_t)c * D + lane * 4);
            acc.x += v.x; acc.y += v.y; acc.z += v.z; acc.w += v.w;
        }
    }
    *(float4*)(g_qagg + (size_t)node * D + lane * 4) = acc;
}

// scores + exp + rowsum fused (no max pass: exp(s) cannot overflow here)
__global__ __launch_bounds__(256)
void score_csr_kernel() {
    int node = (blockIdx.x * blockDim.x + threadIdx.x) >> 5;
    if (node >= N_NODES) return;
    int lane = threadIdx.x & 31;
    int beg = g_off[node], end = g_off[node + 1];

    float4 k = *(const float4*)(g_kact + (size_t)node * D + lane * 4);
    float sum = 0.f;

    for (int e0 = beg; e0 < end; e0 += 32) {
        int myc = (e0 + lane < end) ? g_ecol[e0 + lane] : 0;
        int n = min(32, end - e0);
        float myex = 0.f;
        int j = 0;
        for (; j + 4 <= n; j += 4) {
            float dd[4];
#pragma unroll
            for (int u = 0; u < 4; u++) {
                int c = __shfl_sync(0xffffffffu, myc, j + u);
                float4 q = *(const float4*)(g_qagg + (size_t)c * D + lane * 4);
                dd[u] = k.x * q.x + k.y * q.y + k.z * q.z + k.w * q.w;
            }
#pragma unroll
            for (int o = 16; o > 0; o >>= 1) {
#pragma unroll
                for (int u = 0; u < 4; u++)
                    dd[u] += __shfl_xor_sync(0xffffffffu, dd[u], o);
            }
#pragma unroll
            for (int u = 0; u < 4; u++) {
                float ex = __expf(dd[u] * INV_SQRT_D);
                sum += ex;
                if (lane == j + u) myex = ex;
            }
        }
        for (; j < n; j++) {
            int c = __shfl_sync(0xffffffffu, myc, j);
            float4 q = *(const float4*)(g_qagg + (size_t)c * D + lane * 4);
            float d = k.x * q.x + k.y * q.y + k.z * q.z + k.w * q.w;
#pragma unroll
            for (int o = 16; o > 0; o >>= 1)
                d += __shfl_xor_sync(0xffffffffu, d, o);
            float ex = __expf(d * INV_SQRT_D);
            sum += ex;
            if (lane == j) myex = ex;
        }
        if (e0 + lane < end) g_escore[e0 + lane] = myex;
    }
    if (lane == 0) g_rinv[node] = 1.0f / (sum + 1e-8f);
}

// out[node] = leaky( sum alpha_e * h_proj[col_e] )
__global__ __launch_bounds__(256)
void weighted_csr_kernel(float* __restrict__ out) {
    int node = (blockIdx.x * blockDim.x + threadIdx.x) >> 5;
    if (node >= N_NODES) return;
    int lane = threadIdx.x & 31;
    int beg = g_off[node], end = g_off[node + 1];
    float rinv = g_rinv[node];

    float4 acc = make_float4(0.f, 0.f, 0.f, 0.f);
    for (int e0 = beg; e0 < end; e0 += 32) {
        int in_range = (e0 + lane < end);
        int myc = in_range ? g_ecol[e0 + lane] : 0;
        float mya = in_range ? g_escore[e0 + lane] * rinv : 0.f;
        int n = min(32, end - e0);
        int j = 0;
        for (; j + 4 <= n; j += 4) {
#pragma unroll
            for (int u = 0; u < 4; u++) {
                int c = __shfl_sync(0xffffffffu, myc, j + u);
                float a = __shfl_sync(0xffffffffu, mya, j + u);
                float4 v = *(const float4*)(g_hproj + (size_t)c * D + lane * 4);
                acc.x += a * v.x;
                acc.y += a * v.y;
                acc.z += a * v.z;
                acc.w += a * v.w;
            }
        }
        for (; j < n; j++) {
            int c = __shfl_sync(0xffffffffu, myc, j);
            float a = __shfl_sync(0xffffffffu, mya, j);
            float4 v = *(const float4*)(g_hproj + (size_t)c * D + lane * 4);
            acc.x += a * v.x;
            acc.y += a * v.y;
            acc.z += a * v.z;
            acc.w += a * v.w;
        }
    }
    acc.x = leaky(acc.x);
    acc.y = leaky(acc.y);
    acc.z = leaky(acc.z);
    acc.w = leaky(acc.w);
    *(float4*)(out + (size_t)node * D + lane * 4) = acc;
}

// ================= launch =================
extern "C" void kernel_launch(void* const* d_in, const int* in_sizes, int n_in,
                              void* d_out, int out_size) {
    const float* x  = (const float*)d_in[0];
    const int*  ei  = (const int*)d_in[1];
    const float* Wq = (const float*)d_in[2];
    const float* Wk = (const float*)d_in[3];
    // d_in[4] = W_v : dead in reference
    const float* Wl = (const float*)d_in[5];
    const float* bl = (const float*)d_in[6];
    float* out = (float*)d_out;

    const int* row = ei;
    const int* col = ei + N_EDGES;

    const int eg = (N_EDGES + 255) / 256;
    const int ng = (N_NODES + 255) / 256;
    const int wg = (N_NODES * 32 + 255) / 256;   // warp-per-node grids

    // CSR build
    zero_cnt_kernel<<<ng, 256>>>();
    hist_kernel<<<eg, 256>>>(row);
    scan1_kernel<<<NBLK_SCAN, SCAN_CHUNK>>>();
    scan2_kernel<<<1, 256>>>();
    scan3_kernel<<<ng, 256>>>();
    scatter_kernel<<<eg, 256>>>(row, col);

    // GEMMs
    {
        dim3 grid((N_NODES + BM - 1) / BM, 3);
        gemm3_kernel<<<grid, 256>>>(x, Wq, Wk, Wl, bl);
    }

    // edge phase
    qagg_csr_kernel<<<wg, 256>>>();
    score_csr_kernel<<<wg, 256>>>();
    weighted_csr_kernel<<<wg, 256>>>(out);
}

// round 3
// speedup vs baseline: 2.8358x; 1.0668x over previous
#include <cuda_runtime.h>
#include <math.h>
#include <stdint.h>

#define N_NODES 100000
#define N_EDGES 1600000
#define D 128
#define NEG_SLOPE 0.2f
#define INV_SQRT_D 0.08838834764831843f

#define SCAN_CHUNK 512
#define NBLK_SCAN ((N_NODES + SCAN_CHUNK - 1) / SCAN_CHUNK)   // 196

// ---------------- scratch (no allocs allowed) ----------------
__device__ float g_hq[N_NODES * D];      // x @ W_q
__device__ float g_kact[N_NODES * D];    // leaky_relu(x @ W_k)
__device__ float g_hproj[N_NODES * D];   // x @ W_l + b_l
__device__ float g_qagg[N_NODES * D];    // segment_sum(h_q[col], row)
__device__ float g_escore[N_EDGES];      // exp(score), CSR order
__device__ int   g_cnt[N_NODES];
__device__ int   g_off[N_NODES + 1];
__device__ int   g_cursor[N_NODES];
__device__ int   g_ecol[N_EDGES];        // col indices sorted by row
__device__ int   g_blocksum[NBLK_SCAN];
__device__ int   g_blockbase[NBLK_SCAN];

__device__ __forceinline__ float leaky(float v) {
    return v > 0.0f ? v : NEG_SLOPE * v;
}

// ================= CSR build =================
__global__ void zero_cnt_kernel() {
    int i = blockIdx.x * blockDim.x + threadIdx.x;
    if (i < N_NODES) g_cnt[i] = 0;
}

__global__ void hist_kernel(const int* __restrict__ row) {
    int e = blockIdx.x * blockDim.x + threadIdx.x;
    if (e < N_EDGES) atomicAdd(&g_cnt[__ldg(row + e)], 1);
}

__global__ void scan1_kernel() {
    __shared__ int s[SCAN_CHUNK];
    int b = blockIdx.x, t = threadIdx.x;
    int i = b * SCAN_CHUNK + t;
    int v = (i < N_NODES) ? g_cnt[i] : 0;
    s[t] = v;
    __syncthreads();
    for (int off = 1; off < SCAN_CHUNK; off <<= 1) {
        int add = (t >= off) ? s[t - off] : 0;
        __syncthreads();
        s[t] += add;
        __syncthreads();
    }
    if (i < N_NODES) g_off[i] = s[t] - v;
    if (t == SCAN_CHUNK - 1) g_blocksum[b] = s[t];
}

__global__ void scan2_kernel() {
    __shared__ int s[256];
    int t = threadIdx.x;
    int v = (t < NBLK_SCAN) ? g_blocksum[t] : 0;
    s[t] = v;
    __syncthreads();
    for (int off = 1; off < 256; off <<= 1) {
        int add = (t >= off) ? s[t - off] : 0;
        __syncthreads();
        s[t] += add;
        __syncthreads();
    }
    if (t < NBLK_SCAN) g_blockbase[t] = s[t] - v;
}

__global__ void scan3_kernel() {
    int i = blockIdx.x * blockDim.x + threadIdx.x;
    if (i < N_NODES) {
        int o = g_off[i] + g_blockbase[i / SCAN_CHUNK];
        g_off[i] = o;
        g_cursor[i] = o;
    }
    if (i == 0) g_off[N_NODES] = N_EDGES;
}

__global__ void scatter_kernel(const int* __restrict__ row,
                               const int* __restrict__ col) {
    int e = blockIdx.x * blockDim.x + threadIdx.x;
    if (e >= N_EDGES) return;
    int r = __ldg(row + e);
    int pos = atomicAdd(&g_cursor[r], 1);
    g_ecol[pos] = __ldg(col + e);
}

// ================= tensor-core GEMM (tf32 split, 3-MMA) =================
// grid.y: 0 -> h_q ; 1 -> k_act (leaky) ; 2 -> h_proj (+bias)
#define GBM 128
#define GBK 32
#define AS_LD 36    // 32 + 4 pad  -> bank = 4r + c, conflict-free
#define WS_LD 136   // 128 + 8 pad -> bank = 8k + n, conflict-free

__device__ __forceinline__ void f2tf32pair(float f, uint32_t& hi, uint32_t& lo) {
    uint32_t h;
    asm("cvt.rna.tf32.f32 %0, %1;" : "=r"(h) : "f"(f));
    float l = f - __uint_as_float(h);
    uint32_t lr;
    asm("cvt.rna.tf32.f32 %0, %1;" : "=r"(lr) : "f"(l));
    hi = h; lo = lr;
}

__device__ __forceinline__ void mma_tf32(float c[4], const uint32_t a[4],
                                         const uint32_t b0, const uint32_t b1) {
    asm volatile(
        "mma.sync.aligned.m16n8k8.row.col.f32.tf32.tf32.f32 "
        "{%0,%1,%2,%3}, {%4,%5,%6,%7}, {%8,%9}, {%0,%1,%2,%3};"
        : "+f"(c[0]), "+f"(c[1]), "+f"(c[2]), "+f"(c[3])
        : "r"(a[0]), "r"(a[1]), "r"(a[2]), "r"(a[3]), "r"(b0), "r"(b1));
}

__global__ __launch_bounds__(256, 2)
void gemm3_tc_kernel(const float* __restrict__ x,
                     const float* __restrict__ Wq,
                     const float* __restrict__ Wk,
                     const float* __restrict__ Wl,
                     const float* __restrict__ bl) {
    __shared__ float As[GBM][AS_LD];   // x tile [row][k]
    __shared__ float Ws[GBK][WS_LD];   // W tile [k][n]

    const int wi = blockIdx.y;
    const float* __restrict__ W = (wi == 0) ? Wq : ((wi == 1) ? Wk : Wl);
    float* __restrict__ out = (wi == 0) ? g_hq : ((wi == 1) ? g_kact : g_hproj);

    const int rowBase = blockIdx.x * GBM;
    const int tid = threadIdx.x;
    const int lane = tid & 31;
    const int warp = tid >> 5;
    const int warp_m = warp & 3;       // 4 warps along M: 32 rows each
    const int warp_n = warp >> 2;      // 2 warps along N: 64 cols each
    const int m_base = warp_m * 32;
    const int n_base = warp_n * 64;
    const int lq = lane >> 2;          // 0..7
    const int lr = lane & 3;           // 0..3

    float c[2][8][4];
#pragma unroll
    for (int mt = 0; mt < 2; mt++)
#pragma unroll
        for (int nt = 0; nt < 8; nt++)
#pragma unroll
            for (int i = 0; i < 4; i++) c[mt][nt][i] = 0.f;

    for (int k0 = 0; k0 < D; k0 += GBK) {
        // load x tile: 128 rows x 32 cols = 1024 float4, 4 per thread
#pragma unroll
        for (int i = tid; i < (GBM * GBK) / 4; i += 256) {
            int r = i >> 3;
            int c4 = (i & 7) << 2;
            int gr = rowBase + r;
            float4 v = make_float4(0.f, 0.f, 0.f, 0.f);
            if (gr < N_NODES)
                v = *(const float4*)(x + (size_t)gr * D + k0 + c4);
            *(float4*)&As[r][c4] = v;
        }
        // load W tile: 32 rows x 128 cols = 1024 float4
#pragma unroll
        for (int i = tid; i < (GBK * D) / 4; i += 256) {
            int k = i >> 5;
            int n4 = (i & 31) << 2;
            float4 v = *(const float4*)(W + (size_t)(k0 + k) * D + n4);
            *(float4*)&Ws[k][n4] = v;
        }
        __syncthreads();

#pragma unroll
        for (int ks = 0; ks < GBK / 8; ks++) {
            const int kb = ks * 8;
            uint32_t a_hi[2][4], a_lo[2][4];
#pragma unroll
            for (int mt = 0; mt < 2; mt++) {
                int r0 = m_base + mt * 16 + lq;
                float f0 = As[r0][kb + lr];
                float f1 = As[r0 + 8][kb + lr];
                float f2 = As[r0][kb + lr + 4];
                float f3 = As[r0 + 8][kb + lr + 4];
                f2tf32pair(f0, a_hi[mt][0], a_lo[mt][0]);
                f2tf32pair(f1, a_hi[mt][1], a_lo[mt][1]);
                f2tf32pair(f2, a_hi[mt][2], a_lo[mt][2]);
                f2tf32pair(f3, a_hi[mt][3], a_lo[mt][3]);
            }
#pragma unroll
            for (int nt = 0; nt < 8; nt++) {
                int n0 = n_base + nt * 8 + lq;
                uint32_t b0h, b0l, b1h, b1l;
                f2tf32pair(Ws[kb + lr][n0], b0h, b0l);
                f2tf32pair(Ws[kb + 4 + lr][n0], b1h, b1l);
#pragma unroll
                for (int mt = 0; mt < 2; mt++) {
                    mma_tf32(c[mt][nt], a_hi[mt], b0h, b1h);   // hi*hi
                    mma_tf32(c[mt][nt], a_hi[mt], b0l, b1l);   // hi*lo
                    mma_tf32(c[mt][nt], a_lo[mt], b0h, b1h);   // lo*hi
                }
            }
        }
        __syncthreads();
    }

    // epilogue
#pragma unroll
    for (int mt = 0; mt < 2; mt++) {
#pragma unroll
        for (int half = 0; half < 2; half++) {
            int gr = rowBase + m_base + mt * 16 + lq + half * 8;
            if (gr >= N_NODES) continue;
#pragma unroll
            for (int nt = 0; nt < 8; nt++) {
                int gc = n_base + nt * 8 + lr * 2;
                float v0 = c[mt][nt][half * 2 + 0];
                float v1 = c[mt][nt][half * 2 + 1];
                if (wi == 1) {
                    v0 = leaky(v0);
                    v1 = leaky(v1);
                } else if (wi == 2) {
                    v0 += __ldg(bl + gc + 0);
                    v1 += __ldg(bl + gc + 1);
                }
                float2 st = make_float2(v0, v1);
                *(float2*)(out + (size_t)gr * D + gc) = st;
            }
        }
    }
}

// ================= edge phase (warp per destination node, CSR) =============

// q_agg[node] = sum over incoming edges of h_q[col]
__global__ __launch_bounds__(256)
void qagg_csr_kernel() {
    int node = (blockIdx.x * blockDim.x + threadIdx.x) >> 5;
    if (node >= N_NODES) return;
    int lane = threadIdx.x & 31;
    int beg = g_off[node], end = g_off[node + 1];

    float4 acc = make_float4(0.f, 0.f, 0.f, 0.f);
    for (int e0 = beg; e0 < end; e0 += 32) {
        int myc = (e0 + lane < end) ? g_ecol[e0 + lane] : 0;
        int n = min(32, end - e0);
        int j = 0;
        for (; j + 4 <= n; j += 4) {
            int c0 = __shfl_sync(0xffffffffu, myc, j + 0);
            int c1 = __shfl_sync(0xffffffffu, myc, j + 1);
            int c2 = __shfl_sync(0xffffffffu, myc, j + 2);
            int c3 = __shfl_sync(0xffffffffu, myc, j + 3);
            float4 v0 = *(const float4*)(g_hq + (size_t)c0 * D + lane * 4);
            float4 v1 = *(const float4*)(g_hq + (size_t)c1 * D + lane * 4);
            float4 v2 = *(const float4*)(g_hq + (size_t)c2 * D + lane * 4);
            float4 v3 = *(const float4*)(g_hq + (size_t)c3 * D + lane * 4);
            acc.x += v0.x + v1.x + v2.x + v3.x;
            acc.y += v0.y + v1.y + v2.y + v3.y;
            acc.z += v0.z + v1.z + v2.z + v3.z;
            acc.w += v0.w + v1.w + v2.w + v3.w;
        }
        for (; j < n; j++) {
            int c = __shfl_sync(0xffffffffu, myc, j);
            float4 v = *(const float4*)(g_hq + (size_t)c * D + lane * 4);
            acc.x += v.x; acc.y += v.y; acc.z += v.z; acc.w += v.w;
        }
    }
    *(float4*)(g_qagg + (size_t)node * D + lane * 4) = acc;
}

// fused: scores + exp + rowsum + weighted aggregation + final leaky relu
__global__ __launch_bounds__(256)
void score_weighted_kernel(float* __restrict__ out) {
    int node = (blockIdx.x * blockDim.x + threadIdx.x) >> 5;
    if (node >= N_NODES) return;
    int lane = threadIdx.x & 31;
    int beg = g_off[node], end = g_off[node + 1];

    float4 k = *(const float4*)(g_kact + (size_t)node * D + lane * 4);
    float sum = 0.f;

    // pass 1: exp(score) per edge + replicated row sum
    for (int e0 = beg; e0 < end; e0 += 32) {
        int myc = (e0 + lane < end) ? g_ecol[e0 + lane] : 0;
        int n = min(32, end - e0);
        float myex = 0.f;
        int j = 0;
        for (; j + 4 <= n; j += 4) {
            float dd[4];
#pragma unroll
            for (int u = 0; u < 4; u++) {
                int c = __shfl_sync(0xffffffffu, myc, j + u);
                float4 q = *(const float4*)(g_qagg + (size_t)c * D + lane * 4);
                dd[u] = k.x * q.x + k.y * q.y + k.z * q.z + k.w * q.w;
            }
#pragma unroll
            for (int o = 16; o > 0; o >>= 1) {
#pragma unroll
                for (int u = 0; u < 4; u++)
                    dd[u] += __shfl_xor_sync(0xffffffffu, dd[u], o);
            }
#pragma unroll
            for (int u = 0; u < 4; u++) {
                float ex = __expf(dd[u] * INV_SQRT_D);
                sum += ex;
                if (lane == j + u) myex = ex;
            }
        }
        for (; j < n; j++) {
            int c = __shfl_sync(0xffffffffu, myc, j);
            float4 q = *(const float4*)(g_qagg + (size_t)c * D + lane * 4);
            float d = k.x * q.x + k.y * q.y + k.z * q.z + k.w * q.w;
#pragma unroll
            for (int o = 16; o > 0; o >>= 1)
                d += __shfl_xor_sync(0xffffffffu, d, o);
            float ex = __expf(d * INV_SQRT_D);
            sum += ex;
            if (lane == j) myex = ex;
        }
        if (e0 + lane < end) g_escore[e0 + lane] = myex;
    }

    float rinv = 1.0f / (sum + 1e-8f);   // sum replicated across lanes

    // pass 2: weighted aggregation of h_proj
    float4 acc = make_float4(0.f, 0.f, 0.f, 0.f);
    for (int e0 = beg; e0 < end; e0 += 32) {
        int in_range = (e0 + lane < end);
        int myc = in_range ? g_ecol[e0 + lane] : 0;
        float mya = in_range ? g_escore[e0 + lane] * rinv : 0.f;
        int n = min(32, end - e0);
        int j = 0;
        for (; j + 4 <= n; j += 4) {
#pragma unroll
            for (int u = 0; u < 4; u++) {
                int c = __shfl_sync(0xffffffffu, myc, j + u);
                float a = __shfl_sync(0xffffffffu, mya, j + u);
                float4 v = *(const float4*)(g_hproj + (size_t)c * D + lane * 4);
                acc.x += a * v.x;
                acc.y += a * v.y;
                acc.z += a * v.z;
                acc.w += a * v.w;
            }
        }
        for (; j < n; j++) {
            int c = __shfl_sync(0xffffffffu, myc, j);
            float a = __shfl_sync(0xffffffffu, mya, j);
            float4 v = *(const float4*)(g_hproj + (size_t)c * D + lane * 4);
            acc.x += a * v.x;
            acc.y += a * v.y;
            acc.z += a * v.z;
            acc.w += a * v.w;
        }
    }
    acc.x = leaky(acc.x);
    acc.y = leaky(acc.y);
    acc.z = leaky(acc.z);
    acc.w = leaky(acc.w);
    *(float4*)(out + (size_t)node * D + lane * 4) = acc;
}

// ================= launch =================
extern "C" void kernel_launch(void* const* d_in, const int* in_sizes, int n_in,
                              void* d_out, int out_size) {
    const float* x  = (const float*)d_in[0];
    const int*  ei  = (const int*)d_in[1];
    const float* Wq = (const float*)d_in[2];
    const float* Wk = (const float*)d_in[3];
    // d_in[4] = W_v : dead in reference
    const float* Wl = (const float*)d_in[5];
    const float* bl = (const float*)d_in[6];
    float* out = (float*)d_out;

    const int* row = ei;
    const int* col = ei + N_EDGES;

    const int eg = (N_EDGES + 255) / 256;
    const int ng = (N_NODES + 255) / 256;
    const int wg = (N_NODES * 32 + 255) / 256;

    // CSR build
    zero_cnt_kernel<<<ng, 256>>>();
    hist_kernel<<<eg, 256>>>(row);
    scan1_kernel<<<NBLK_SCAN, SCAN_CHUNK>>>();
    scan2_kernel<<<1, 256>>>();
    scan3_kernel<<<ng, 256>>>();
    scatter_kernel<<<eg, 256>>>(row, col);

    // tensor-core GEMMs
    {
        dim3 grid((N_NODES + GBM - 1) / GBM, 3);
        gemm3_tc_kernel<<<grid, 256>>>(x, Wq, Wk, Wl, bl);
    }

    // edge phase
    qagg_csr_kernel<<<wg, 256>>>();
    score_weighted_kernel<<<wg, 256>>>(out);
}